// round 15
// baseline (speedup 1.0000x reference)
#include <cuda_runtime.h>
#include <cuda_bf16.h>
#include <cuda_fp16.h>

// ---------------------------------------------------------------------------
// Attention_9947144257674 — round 15
//   attention restructured for smem-crossbar relief: 4 warps x 32 q-rows
//   (was 8 x 16) -> K/V fragments reused 2x more, ~507 -> ~147 B/mma.
//   Gemm + prep unchanged from round 14. Numerics identical.
// ---------------------------------------------------------------------------

#define BSROWS 8192
#define DM     1024

__device__ __half g_x16 [(size_t)BSROWS * DM];
__device__ __half g_wt16[(size_t)4 * DM * DM];   // [slice][c][e]
__device__ __half g_q16 [(size_t)BSROWS * DM];   // prescaled Q
__device__ __half g_k16 [(size_t)BSROWS * DM];
__device__ __half g_vt16[(size_t)64 * 64 * 2048];// V^T [b*16+h][d][s]
__device__ __half g_z16 [(size_t)BSROWS * DM];

// ---------------------------------------------------------------------------
__device__ __forceinline__ unsigned smem_u32(const void* p) {
    unsigned a;
    asm("{ .reg .u64 t; cvta.to.shared.u64 t, %1; cvt.u32.u64 %0, t; }"
        : "=r"(a) : "l"(p));
    return a;
}

__device__ __forceinline__ void ldmx4(unsigned addr, unsigned& r0, unsigned& r1,
                                      unsigned& r2, unsigned& r3) {
    asm volatile("ldmatrix.sync.aligned.m8n8.x4.shared.b16 {%0,%1,%2,%3}, [%4];"
                 : "=r"(r0), "=r"(r1), "=r"(r2), "=r"(r3) : "r"(addr));
}

__device__ __forceinline__ void mmafp16(float* c, const unsigned* a,
                                        unsigned b0, unsigned b1) {
    asm volatile(
        "mma.sync.aligned.m16n8k16.row.col.f32.f16.f16.f32 "
        "{%0,%1,%2,%3}, {%4,%5,%6,%7}, {%8,%9}, {%0,%1,%2,%3};"
        : "+f"(c[0]), "+f"(c[1]), "+f"(c[2]), "+f"(c[3])
        : "r"(a[0]), "r"(a[1]), "r"(a[2]), "r"(a[3]), "r"(b0), "r"(b1));
}

#define CPASYNC16(sa, g) \
    asm volatile("cp.async.cg.shared.global [%0], [%1], 16;" :: "r"(sa), "l"(g) : "memory")
#define CPCOMMIT() asm volatile("cp.async.commit_group;" ::: "memory")
#define CPWAIT0()  asm volatile("cp.async.wait_group 0;" ::: "memory")
#define CPWAIT1()  asm volatile("cp.async.wait_group 1;" ::: "memory")

__device__ __forceinline__ unsigned cvt_f16x2(float lo, float hi) {
    unsigned r;
    asm("cvt.rn.f16x2.f32 %0, %1, %2;" : "=r"(r) : "f"(hi), "f"(lo));
    return r;
}
__device__ __forceinline__ unsigned ex2h2(unsigned x) {
    unsigned y;
    asm("ex2.approx.f16x2 %0, %1;" : "=r"(y) : "r"(x));
    return y;
}
#define ONESH2 0x3C003C00u

// ---------------------------------------------------------------------------
// fused prep (unchanged)
// ---------------------------------------------------------------------------
__global__ __launch_bounds__(256) void prep(const float* __restrict__ x,
                                            const float* __restrict__ WQ,
                                            const float* __restrict__ WK,
                                            const float* __restrict__ WV,
                                            const float* __restrict__ WO) {
    const int bid = blockIdx.x;
    if (bid >= 4096) {
        size_t i = ((size_t)(bid - 4096) * 256 + threadIdx.x) * 4;
        float4 v = *reinterpret_cast<const float4*>(x + i);
        *reinterpret_cast<__half2*>(g_x16 + i)     = __floats2half2_rn(v.x, v.y);
        *reinterpret_cast<__half2*>(g_x16 + i + 2) = __floats2half2_rn(v.z, v.w);
        return;
    }
    const int m  = bid >> 10;
    const int c0 = ((bid >> 5) & 31) * 32;
    const int e0 = (bid & 31) * 32;
    const float* W = (m == 0) ? WQ : (m == 1) ? WK : (m == 2) ? WV : WO;
    __half* D = g_wt16 + (size_t)m * DM * DM;

    __shared__ float t[32][33];
    const int tx = threadIdx.x & 31, ty = threadIdx.x >> 5;

    #pragma unroll
    for (int j = 0; j < 4; j++) {
        int c = c0 + tx, e = e0 + ty + j * 8;
        size_t src = (m < 3)
            ? ((size_t)(c >> 6) * 65536 + (size_t)e * 64 + (c & 63))
            : ((size_t)e * 1024 + c);
        t[tx][ty + j * 8] = W[src];
    }
    __syncthreads();
    #pragma unroll
    for (int j = 0; j < 4; j++) {
        int e = e0 + tx, c = c0 + ty + j * 8;
        D[(size_t)c * 1024 + e] = __float2half_rn(t[ty + j * 8][tx]);
    }
}

// ---------------------------------------------------------------------------
// mma GEMM (unchanged from round 14)
// ---------------------------------------------------------------------------
#define GS       144
#define GARR     18432
#define GBUF     36864
#define SMEM_G   110592
#define TSTRIDE  136

__global__ __launch_bounds__(256, 2) void gemm_mma(
    const __half* __restrict__ A16,
    const float* __restrict__ bQ, const float* __restrict__ bK,
    const float* __restrict__ bV, float* __restrict__ out_f32, int o_mode)
{
    extern __shared__ __align__(128) char sm[];
    const int tid  = threadIdx.x;
    const int lane = tid & 31, w = tid >> 5;
    const int wm = w >> 1, wn = w & 1;
    const int z  = blockIdx.z;
    const int bm = blockIdx.y * 128, bn = blockIdx.x * 128;

    const int slice = o_mode ? 3 : z;
    const __half* Bw = g_wt16 + (size_t)slice * DM * DM + (size_t)bn * DM;
    const __half* Aa = A16 + (size_t)bm * DM;
    const float* bias = o_mode ? bQ : (z == 0 ? bQ : (z == 1 ? bK : bV));
    const float oscale = (!o_mode && z == 0) ? (0.125f * 1.4426950408889634f) : 1.0f;

    const unsigned sbase = smem_u32(sm);

    float acc[2][8][4];
    #pragma unroll
    for (int i = 0; i < 2; i++)
        #pragma unroll
        for (int j = 0; j < 8; j++)
            #pragma unroll
            for (int e = 0; e < 4; e++) acc[i][j][e] = 0.f;

    const __half* srcs[2] = {Aa, Bw};

    auto fill = [&](int buf, int k0) {
        #pragma unroll
        for (int i = 0; i < 8; i++) {
            int c = tid + i * 256;
            int a = c >> 10;
            int row = (c >> 3) & 127, q = c & 7;
            unsigned sa = sbase + buf * GBUF + a * GARR + row * GS + q * 16;
            CPASYNC16(sa, srcs[a] + (size_t)row * DM + k0 + q * 8);
        }
        CPCOMMIT();
    };

    fill(0, 0);
    fill(1, 64);
    int buf = 0;
    #pragma unroll 1
    for (int ci = 0; ci < 16; ci++) {
        CPWAIT1();
        __syncthreads();

        const unsigned Ab = sbase + buf * GBUF;
        const unsigned Bb = Ab + GARR;
        #pragma unroll
        for (int ks = 0; ks < 4; ks++) {
            const int kb = ks * 32;
            unsigned ah[2][4];
            #pragma unroll
            for (int i = 0; i < 2; i++) {
                unsigned aaddr = Ab + (wm * 32 + i * 16 + (lane & 15)) * GS + kb
                                 + ((lane >> 4) & 1) * 16;
                ldmx4(aaddr, ah[i][0], ah[i][1], ah[i][2], ah[i][3]);
            }
            #pragma unroll
            for (int jj = 0; jj < 4; jj++) {
                unsigned baddr = Bb + (wn * 64 + jj * 16 + (lane & 7)
                                 + ((lane >> 4) & 1) * 8) * GS + kb
                                 + ((lane >> 3) & 1) * 16;
                unsigned b0, b1, b2, b3;
                ldmx4(baddr, b0, b1, b2, b3);
                #pragma unroll
                for (int i = 0; i < 2; i++) {
                    mmafp16(acc[i][jj * 2],     ah[i], b0, b1);
                    mmafp16(acc[i][jj * 2 + 1], ah[i], b2, b3);
                }
            }
        }

        if (ci + 2 < 16) fill((buf + 2) % 3, (ci + 2) * 64);
        buf = (buf + 1) % 3;
    }
    CPWAIT0();
    __syncthreads();

    const bool vmode = (!o_mode && z == 2);
    __half* stg = reinterpret_cast<__half*>(sm);

    #pragma unroll
    for (int i = 0; i < 2; i++) {
        const int rl = wm * 32 + i * 16 + (lane >> 2);
        const int row = bm + rl;
        #pragma unroll
        for (int j = 0; j < 8; j++) {
            const int cl = wn * 64 + j * 8 + (lane & 3) * 2;
            const int col = bn + cl;
            float v0 = (acc[i][j][0] + bias[col])     * oscale;
            float v1 = (acc[i][j][1] + bias[col + 1]) * oscale;
            float v2 = (acc[i][j][2] + bias[col])     * oscale;
            float v3 = (acc[i][j][3] + bias[col + 1]) * oscale;
            if (o_mode) {
                float2 a = {v0, v1}, b2 = {v2, v3};
                *reinterpret_cast<float2*>(&out_f32[(size_t)row * DM + col]) = a;
                *reinterpret_cast<float2*>(&out_f32[(size_t)(row + 8) * DM + col]) = b2;
            } else if (vmode) {
                stg[cl * TSTRIDE + rl]           = __float2half_rn(v0);
                stg[(cl + 1) * TSTRIDE + rl]     = __float2half_rn(v1);
                stg[cl * TSTRIDE + rl + 8]       = __float2half_rn(v2);
                stg[(cl + 1) * TSTRIDE + rl + 8] = __float2half_rn(v3);
            } else {
                __half* dst = (z == 0) ? g_q16 : g_k16;
                *reinterpret_cast<__half2*>(&dst[(size_t)row * DM + col]) =
                    __floats2half2_rn(v0, v1);
                *reinterpret_cast<__half2*>(&dst[(size_t)(row + 8) * DM + col]) =
                    __floats2half2_rn(v2, v3);
            }
        }
    }

    if (vmode) {
        __syncthreads();
        const int bb = bm >> 11;
        const int c  = tid >> 1, hf = tid & 1;
        const int gcol = bn + c;
        const int hh = gcol >> 6, d = gcol & 63;
        const __half* srcr = stg + c * TSTRIDE + hf * 64;
        __half* dstr = g_vt16 + ((size_t)(bb * 16 + hh) * 64 + d) * 2048
                       + (bm & 2047) + hf * 64;
        #pragma unroll
        for (int u = 0; u < 8; u++)
            *reinterpret_cast<uint4*>(dstr + u * 8) =
                *reinterpret_cast<const uint4*>(srcr + u * 8);
    }
}

// ---------------------------------------------------------------------------
// flash attention: 4 warps x 32 q-rows (BQ=128), 64-key tiles, double-buffered.
// smem: Q 128x144 + 2 x (K 64x144 + V^T 64x144) = 55296
// ---------------------------------------------------------------------------
#define AS      144
#define AARR    9216             // 64*144
#define QARR    18432            // 128*144
#define KVBASE  QARR
#define KVBUF   (2 * AARR)
#define SMEM_A  55296
#define MASKV   (-60000.0f)

__global__ __launch_bounds__(128, 3) void attn_mma()
{
    extern __shared__ __align__(128) char sm[];
    const int tid = threadIdx.x, lane = tid & 31, w = tid >> 5;  // w: 0..3
    const int qt = (int)gridDim.x - 1 - (int)blockIdx.x;
    const int bh = blockIdx.y;
    const int b = bh >> 4, h = bh & 15;

    const unsigned sb = smem_u32(sm);
    const size_t qrow0 = (size_t)b * 2048 + (size_t)qt * 128;
    const size_t hoff  = (size_t)h * 64;

    // Q tile load: 128 rows x 8 x 16B = 1024 transfers / 128 threads
    {
        const __half* q16 = g_q16 + qrow0 * DM + hoff;
        #pragma unroll
        for (int i = 0; i < 8; i++) {
            int c = tid + i * 128;
            int r = c >> 3, q = c & 7;
            unsigned sa = sb + r * AS + q * 16;
            CPASYNC16(sa, q16 + (size_t)r * DM + q * 8);
        }
        CPCOMMIT(); CPWAIT0();
        __syncthreads();
    }
    // per-warp Q fragments: rows w*32 + mi*16
    unsigned qf[2][4][4];
    #pragma unroll
    for (int mi = 0; mi < 2; mi++)
        #pragma unroll
        for (int ks = 0; ks < 4; ks++) {
            unsigned aaddr = sb + (w * 32 + mi * 16 + (lane & 15)) * AS + ks * 32
                             + ((lane >> 4) & 1) * 16;
            ldmx4(aaddr, qf[mi][ks][0], qf[mi][ks][1], qf[mi][ks][2], qf[mi][ks][3]);
        }

    float o[2][8][4];
    #pragma unroll
    for (int mi = 0; mi < 2; mi++)
        #pragma unroll
        for (int j = 0; j < 8; j++)
            #pragma unroll
            for (int e = 0; e < 4; e++) o[mi][j][e] = 0.f;
    float lacc[2][4] = {{0.f, 0.f, 0.f, 0.f}, {0.f, 0.f, 0.f, 0.f}};

    const __half* kk16 = g_k16 + (size_t)b * 2048 * DM + hoff;
    const __half* vt   = g_vt16 + (size_t)bh * 64 * 2048;

    const int nk = 2 * qt + 2;   // 64-key tiles

    auto fillkv = [&](int buf, int kt) {
        #pragma unroll
        for (int i = 0; i < 8; i++) {
            int c = tid + i * 128;            // 0..1023
            int a = c >> 9;                   // 0=K 1=V^T
            int r = (c >> 3) & 63, q = c & 7;
            unsigned sa = sb + KVBASE + buf * KVBUF + a * AARR + r * AS + q * 16;
            const __half* src;
            size_t off;
            if (a == 0) { src = kk16; off = (size_t)(kt * 64 + r) * DM + q * 8; }
            else        { src = vt;   off = (size_t)r * 2048 + kt * 64 + q * 8; }
            CPASYNC16(sa, src + off);
        }
        CPCOMMIT();
    };

    fillkv(0, 0);
    #pragma unroll 1
    for (int kt = 0; kt < nk; kt++) {
        const int buf = kt & 1;
        if (kt + 1 < nk) { fillkv(buf ^ 1, kt + 1); CPWAIT1(); }
        else             { CPWAIT0(); }
        __syncthreads();

        const unsigned Kb = sb + KVBASE + buf * KVBUF;
        const unsigned Vb = Kb + AARR;

        // ---- S = Q K^T : 32 q-rows x 64 keys per warp ----
        float s[2][8][4];
        #pragma unroll
        for (int mi = 0; mi < 2; mi++)
            #pragma unroll
            for (int j = 0; j < 8; j++)
                #pragma unroll
                for (int e = 0; e < 4; e++) s[mi][j][e] = 0.f;

        #pragma unroll
        for (int ks = 0; ks < 4; ks++) {
            const int kb = ks * 32;
            #pragma unroll
            for (int jj = 0; jj < 4; jj++) {
                unsigned baddr = Kb + (jj * 16 + (lane & 7) + ((lane >> 4) & 1) * 8) * AS
                                 + kb + ((lane >> 3) & 1) * 16;
                unsigned b0, b1, b2, b3;
                ldmx4(baddr, b0, b1, b2, b3);
                #pragma unroll
                for (int mi = 0; mi < 2; mi++) {
                    mmafp16(s[mi][jj * 2],     qf[mi][ks], b0, b1);
                    mmafp16(s[mi][jj * 2 + 1], qf[mi][ks], b2, b3);
                }
            }
        }

        // ---- causal mask ----
        if (kt >= 2 * qt) {
            #pragma unroll
            for (int mi = 0; mi < 2; mi++) {
                const int r0 = qt * 128 + w * 32 + mi * 16 + (lane >> 2), r1 = r0 + 8;
                #pragma unroll
                for (int j = 0; j < 8; j++) {
                    const int cb = kt * 64 + j * 8 + (lane & 3) * 2;
                    if (cb     > r0) s[mi][j][0] = MASKV;
                    if (cb + 1 > r0) s[mi][j][1] = MASKV;
                    if (cb     > r1) s[mi][j][2] = MASKV;
                    if (cb + 1 > r1) s[mi][j][3] = MASKV;
                }
            }
        }

        // ---- exp2 in f16x2 ----
        unsigned ph[2][8][2];
        #pragma unroll
        for (int mi = 0; mi < 2; mi++)
            #pragma unroll
            for (int j = 0; j < 8; j++) {
                ph[mi][j][0] = ex2h2(cvt_f16x2(s[mi][j][0], s[mi][j][1]));
                ph[mi][j][1] = ex2h2(cvt_f16x2(s[mi][j][2], s[mi][j][3]));
            }

        // ---- O += P V, row sums via ones-mma ----
        #pragma unroll
        for (int kk = 0; kk < 4; kk++) {
            const int t0 = kk * 2, t1 = kk * 2 + 1;
            unsigned pA[2][4];
            #pragma unroll
            for (int mi = 0; mi < 2; mi++) {
                pA[mi][0] = ph[mi][t0][0]; pA[mi][1] = ph[mi][t0][1];
                pA[mi][2] = ph[mi][t1][0]; pA[mi][3] = ph[mi][t1][1];
                mmafp16(lacc[mi], pA[mi], ONESH2, ONESH2);
            }
            #pragma unroll
            for (int jj = 0; jj < 4; jj++) {
                unsigned baddr = Vb + (jj * 16 + (lane & 7) + ((lane >> 4) & 1) * 8) * AS
                                 + kk * 32 + ((lane >> 3) & 1) * 16;
                unsigned b0, b1, b2, b3;
                ldmx4(baddr, b0, b1, b2, b3);
                #pragma unroll
                for (int mi = 0; mi < 2; mi++) {
                    mmafp16(o[mi][jj * 2],     pA[mi], b0, b1);
                    mmafp16(o[mi][jj * 2 + 1], pA[mi], b2, b3);
                }
            }
        }
        __syncthreads();
    }

    #pragma unroll
    for (int mi = 0; mi < 2; mi++) {
        const float inv0 = 1.0f / lacc[mi][0], inv1 = 1.0f / lacc[mi][2];
        const size_t row0 = qrow0 + w * 32 + mi * 16 + (lane >> 2);
        #pragma unroll
        for (int j = 0; j < 8; j++) {
            const size_t col = hoff + j * 8 + (lane & 3) * 2;
            *reinterpret_cast<__half2*>(&g_z16[row0 * DM + col]) =
                __floats2half2_rn(o[mi][j][0] * inv0, o[mi][j][1] * inv0);
            *reinterpret_cast<__half2*>(&g_z16[(row0 + 8) * DM + col]) =
                __floats2half2_rn(o[mi][j][2] * inv1, o[mi][j][3] * inv1);
        }
    }
}

// ---------------------------------------------------------------------------
extern "C" void kernel_launch(void* const* d_in, const int* in_sizes, int n_in,
                              void* d_out, int out_size)
{
    (void)in_sizes; (void)n_in; (void)out_size;
    const float* x  = (const float*)d_in[0];
    const float* WQ = (const float*)d_in[1];
    const float* bQ = (const float*)d_in[2];
    const float* WK = (const float*)d_in[3];
    const float* bK = (const float*)d_in[4];
    const float* WV = (const float*)d_in[5];
    const float* bV = (const float*)d_in[6];
    const float* WO = (const float*)d_in[7];
    const float* bO = (const float*)d_in[8];
    float* out = (float*)d_out;

    cudaFuncSetAttribute(gemm_mma, cudaFuncAttributeMaxDynamicSharedMemorySize, SMEM_G);
    cudaFuncSetAttribute(attn_mma, cudaFuncAttributeMaxDynamicSharedMemorySize, SMEM_A);

    __half *x16, *z16;
    cudaGetSymbolAddress((void**)&x16, g_x16);
    cudaGetSymbolAddress((void**)&z16, g_z16);

    prep<<<12288, 256>>>(x, WQ, WK, WV, WO);

    gemm_mma<<<dim3(8, 64, 3), 256, SMEM_G>>>(x16, bQ, bK, bV, nullptr, 0);

    attn_mma<<<dim3(16, 64), 128, SMEM_A>>>();

    gemm_mma<<<dim3(8, 64, 1), 256, SMEM_G>>>(z16, bO, bO, bO, out, 1);
}

// round 16
// speedup vs baseline: 1.1158x; 1.1158x over previous
#include <cuda_runtime.h>
#include <cuda_bf16.h>
#include <cuda_fp16.h>

// ---------------------------------------------------------------------------
// Attention_9947144257674 — round 16: revert attention to round-14 config
// (round 15's 32-q-rows/warp spilled registers: 190 needed vs 166 cap).
// prep: 8 elems/thread. Gemm unchanged. Numerics identical (5.3231e-4).
// ---------------------------------------------------------------------------

#define BSROWS 8192
#define DM     1024

__device__ __half g_x16 [(size_t)BSROWS * DM];
__device__ __half g_wt16[(size_t)4 * DM * DM];   // [slice][c][e]
__device__ __half g_q16 [(size_t)BSROWS * DM];   // prescaled Q
__device__ __half g_k16 [(size_t)BSROWS * DM];
__device__ __half g_vt16[(size_t)64 * 64 * 2048];// V^T [b*16+h][d][s]
__device__ __half g_z16 [(size_t)BSROWS * DM];

// ---------------------------------------------------------------------------
__device__ __forceinline__ unsigned smem_u32(const void* p) {
    unsigned a;
    asm("{ .reg .u64 t; cvta.to.shared.u64 t, %1; cvt.u32.u64 %0, t; }"
        : "=r"(a) : "l"(p));
    return a;
}

__device__ __forceinline__ void ldmx4(unsigned addr, unsigned& r0, unsigned& r1,
                                      unsigned& r2, unsigned& r3) {
    asm volatile("ldmatrix.sync.aligned.m8n8.x4.shared.b16 {%0,%1,%2,%3}, [%4];"
                 : "=r"(r0), "=r"(r1), "=r"(r2), "=r"(r3) : "r"(addr));
}

__device__ __forceinline__ void mmafp16(float* c, const unsigned* a,
                                        unsigned b0, unsigned b1) {
    asm volatile(
        "mma.sync.aligned.m16n8k16.row.col.f32.f16.f16.f32 "
        "{%0,%1,%2,%3}, {%4,%5,%6,%7}, {%8,%9}, {%0,%1,%2,%3};"
        : "+f"(c[0]), "+f"(c[1]), "+f"(c[2]), "+f"(c[3])
        : "r"(a[0]), "r"(a[1]), "r"(a[2]), "r"(a[3]), "r"(b0), "r"(b1));
}

#define CPASYNC16(sa, g) \
    asm volatile("cp.async.cg.shared.global [%0], [%1], 16;" :: "r"(sa), "l"(g) : "memory")
#define CPCOMMIT() asm volatile("cp.async.commit_group;" ::: "memory")
#define CPWAIT0()  asm volatile("cp.async.wait_group 0;" ::: "memory")
#define CPWAIT1()  asm volatile("cp.async.wait_group 1;" ::: "memory")

__device__ __forceinline__ unsigned cvt_f16x2(float lo, float hi) {
    unsigned r;
    asm("cvt.rn.f16x2.f32 %0, %1, %2;" : "=r"(r) : "f"(hi), "f"(lo));
    return r;
}
__device__ __forceinline__ unsigned ex2h2(unsigned x) {
    unsigned y;
    asm("ex2.approx.f16x2 %0, %1;" : "=r"(y) : "r"(x));
    return y;
}
#define ONESH2 0x3C003C00u

// ---------------------------------------------------------------------------
// fused prep: blocks [0, 4096) -> weight transpose, [4096, 8192) -> x cvt
// (8 elems/thread)
// ---------------------------------------------------------------------------
__global__ __launch_bounds__(256) void prep(const float* __restrict__ x,
                                            const float* __restrict__ WQ,
                                            const float* __restrict__ WK,
                                            const float* __restrict__ WV,
                                            const float* __restrict__ WO) {
    const int bid = blockIdx.x;
    if (bid >= 4096) {
        size_t i = ((size_t)(bid - 4096) * 256 + threadIdx.x) * 8;
        float4 v0 = *reinterpret_cast<const float4*>(x + i);
        float4 v1 = *reinterpret_cast<const float4*>(x + i + 4);
        uint2 o0, o1;
        o0.x = cvt_f16x2(v0.x, v0.y); o0.y = cvt_f16x2(v0.z, v0.w);
        o1.x = cvt_f16x2(v1.x, v1.y); o1.y = cvt_f16x2(v1.z, v1.w);
        *reinterpret_cast<uint2*>(g_x16 + i)     = o0;
        *reinterpret_cast<uint2*>(g_x16 + i + 4) = o1;
        return;
    }
    const int m  = bid >> 10;
    const int c0 = ((bid >> 5) & 31) * 32;
    const int e0 = (bid & 31) * 32;
    const float* W = (m == 0) ? WQ : (m == 1) ? WK : (m == 2) ? WV : WO;
    __half* D = g_wt16 + (size_t)m * DM * DM;

    __shared__ float t[32][33];
    const int tx = threadIdx.x & 31, ty = threadIdx.x >> 5;

    #pragma unroll
    for (int j = 0; j < 4; j++) {
        int c = c0 + tx, e = e0 + ty + j * 8;
        size_t src = (m < 3)
            ? ((size_t)(c >> 6) * 65536 + (size_t)e * 64 + (c & 63))
            : ((size_t)e * 1024 + c);
        t[tx][ty + j * 8] = W[src];
    }
    __syncthreads();
    #pragma unroll
    for (int j = 0; j < 4; j++) {
        int e = e0 + tx, c = c0 + ty + j * 8;
        D[(size_t)c * 1024 + e] = __float2half_rn(t[ty + j * 8][tx]);
    }
}

// ---------------------------------------------------------------------------
// mma GEMM (round-14): 128x128 tile, K-chunk 64, 3-stage ring, 2 CTAs/SM.
// ---------------------------------------------------------------------------
#define GS       144
#define GARR     18432
#define GBUF     36864
#define SMEM_G   110592
#define TSTRIDE  136

__global__ __launch_bounds__(256, 2) void gemm_mma(
    const __half* __restrict__ A16,
    const float* __restrict__ bQ, const float* __restrict__ bK,
    const float* __restrict__ bV, float* __restrict__ out_f32, int o_mode)
{
    extern __shared__ __align__(128) char sm[];
    const int tid  = threadIdx.x;
    const int lane = tid & 31, w = tid >> 5;
    const int wm = w >> 1, wn = w & 1;
    const int z  = blockIdx.z;
    const int bm = blockIdx.y * 128, bn = blockIdx.x * 128;

    const int slice = o_mode ? 3 : z;
    const __half* Bw = g_wt16 + (size_t)slice * DM * DM + (size_t)bn * DM;
    const __half* Aa = A16 + (size_t)bm * DM;
    const float* bias = o_mode ? bQ : (z == 0 ? bQ : (z == 1 ? bK : bV));
    const float oscale = (!o_mode && z == 0) ? (0.125f * 1.4426950408889634f) : 1.0f;

    const unsigned sbase = smem_u32(sm);

    float acc[2][8][4];
    #pragma unroll
    for (int i = 0; i < 2; i++)
        #pragma unroll
        for (int j = 0; j < 8; j++)
            #pragma unroll
            for (int e = 0; e < 4; e++) acc[i][j][e] = 0.f;

    const __half* srcs[2] = {Aa, Bw};

    auto fill = [&](int buf, int k0) {
        #pragma unroll
        for (int i = 0; i < 8; i++) {
            int c = tid + i * 256;
            int a = c >> 10;
            int row = (c >> 3) & 127, q = c & 7;
            unsigned sa = sbase + buf * GBUF + a * GARR + row * GS + q * 16;
            CPASYNC16(sa, srcs[a] + (size_t)row * DM + k0 + q * 8);
        }
        CPCOMMIT();
    };

    fill(0, 0);
    fill(1, 64);
    int buf = 0;
    #pragma unroll 1
    for (int ci = 0; ci < 16; ci++) {
        CPWAIT1();
        __syncthreads();

        const unsigned Ab = sbase + buf * GBUF;
        const unsigned Bb = Ab + GARR;
        #pragma unroll
        for (int ks = 0; ks < 4; ks++) {
            const int kb = ks * 32;
            unsigned ah[2][4];
            #pragma unroll
            for (int i = 0; i < 2; i++) {
                unsigned aaddr = Ab + (wm * 32 + i * 16 + (lane & 15)) * GS + kb
                                 + ((lane >> 4) & 1) * 16;
                ldmx4(aaddr, ah[i][0], ah[i][1], ah[i][2], ah[i][3]);
            }
            #pragma unroll
            for (int jj = 0; jj < 4; jj++) {
                unsigned baddr = Bb + (wn * 64 + jj * 16 + (lane & 7)
                                 + ((lane >> 4) & 1) * 8) * GS + kb
                                 + ((lane >> 3) & 1) * 16;
                unsigned b0, b1, b2, b3;
                ldmx4(baddr, b0, b1, b2, b3);
                #pragma unroll
                for (int i = 0; i < 2; i++) {
                    mmafp16(acc[i][jj * 2],     ah[i], b0, b1);
                    mmafp16(acc[i][jj * 2 + 1], ah[i], b2, b3);
                }
            }
        }

        if (ci + 2 < 16) fill((buf + 2) % 3, (ci + 2) * 64);
        buf = (buf + 1) % 3;
    }
    CPWAIT0();
    __syncthreads();

    const bool vmode = (!o_mode && z == 2);
    __half* stg = reinterpret_cast<__half*>(sm);

    #pragma unroll
    for (int i = 0; i < 2; i++) {
        const int rl = wm * 32 + i * 16 + (lane >> 2);
        const int row = bm + rl;
        #pragma unroll
        for (int j = 0; j < 8; j++) {
            const int cl = wn * 64 + j * 8 + (lane & 3) * 2;
            const int col = bn + cl;
            float v0 = (acc[i][j][0] + bias[col])     * oscale;
            float v1 = (acc[i][j][1] + bias[col + 1]) * oscale;
            float v2 = (acc[i][j][2] + bias[col])     * oscale;
            float v3 = (acc[i][j][3] + bias[col + 1]) * oscale;
            if (o_mode) {
                float2 a = {v0, v1}, b2 = {v2, v3};
                *reinterpret_cast<float2*>(&out_f32[(size_t)row * DM + col]) = a;
                *reinterpret_cast<float2*>(&out_f32[(size_t)(row + 8) * DM + col]) = b2;
            } else if (vmode) {
                stg[cl * TSTRIDE + rl]           = __float2half_rn(v0);
                stg[(cl + 1) * TSTRIDE + rl]     = __float2half_rn(v1);
                stg[cl * TSTRIDE + rl + 8]       = __float2half_rn(v2);
                stg[(cl + 1) * TSTRIDE + rl + 8] = __float2half_rn(v3);
            } else {
                __half* dst = (z == 0) ? g_q16 : g_k16;
                *reinterpret_cast<__half2*>(&dst[(size_t)row * DM + col]) =
                    __floats2half2_rn(v0, v1);
                *reinterpret_cast<__half2*>(&dst[(size_t)(row + 8) * DM + col]) =
                    __floats2half2_rn(v2, v3);
            }
        }
    }

    if (vmode) {
        __syncthreads();
        const int bb = bm >> 11;
        const int c  = tid >> 1, hf = tid & 1;
        const int gcol = bn + c;
        const int hh = gcol >> 6, d = gcol & 63;
        const __half* srcr = stg + c * TSTRIDE + hf * 64;
        __half* dstr = g_vt16 + ((size_t)(bb * 16 + hh) * 64 + d) * 2048
                       + (bm & 2047) + hf * 64;
        #pragma unroll
        for (int u = 0; u < 8; u++)
            *reinterpret_cast<uint4*>(dstr + u * 8) =
                *reinterpret_cast<const uint4*>(srcr + u * 8);
    }
}

// ---------------------------------------------------------------------------
// flash attention (round-14 config): BQ=128, 8 warps x 16 q-rows,
// 128-key tiles (two 64-key sub-passes), double-buffered, one sync/tile.
// ---------------------------------------------------------------------------
#define AS      144
#define VS      272
#define QARR    18432
#define K_ARR   18432
#define V_ARR   17408
#define KVBASE  QARR
#define KVBUF   (K_ARR + V_ARR)
#define SMEM_A  90112
#define MASKV   (-60000.0f)

__global__ __launch_bounds__(256, 2) void attn_mma()
{
    extern __shared__ __align__(128) char sm[];
    const int tid = threadIdx.x, lane = tid & 31, w = tid >> 5;
    const int qt = (int)gridDim.x - 1 - (int)blockIdx.x;
    const int bh = blockIdx.y;
    const int b = bh >> 4, h = bh & 15;

    const unsigned sb = smem_u32(sm);
    const size_t qrow0 = (size_t)b * 2048 + (size_t)qt * 128;
    const size_t hoff  = (size_t)h * 64;

    {
        const __half* q16 = g_q16 + qrow0 * DM + hoff;
        #pragma unroll
        for (int i = 0; i < 4; i++) {
            int c = tid + i * 256;
            int r = c >> 3, q = c & 7;
            unsigned sa = sb + r * AS + q * 16;
            CPASYNC16(sa, q16 + (size_t)r * DM + q * 8);
        }
        CPCOMMIT(); CPWAIT0();
        __syncthreads();
    }
    unsigned qf[4][4];
    #pragma unroll
    for (int ks = 0; ks < 4; ks++) {
        unsigned aaddr = sb + (w * 16 + (lane & 15)) * AS + ks * 32
                         + ((lane >> 4) & 1) * 16;
        ldmx4(aaddr, qf[ks][0], qf[ks][1], qf[ks][2], qf[ks][3]);
    }

    float o[8][4];
    #pragma unroll
    for (int j = 0; j < 8; j++)
        #pragma unroll
        for (int e = 0; e < 4; e++) o[j][e] = 0.f;
    float lacc[4] = {0.f, 0.f, 0.f, 0.f};

    const __half* kk16 = g_k16 + (size_t)b * 2048 * DM + hoff;
    const __half* vt   = g_vt16 + (size_t)bh * 64 * 2048;

    const int nk = qt + 1;

    auto fillkv = [&](int buf, int kt) {
        #pragma unroll
        for (int i = 0; i < 8; i++) {
            int c = tid + i * 256;
            if (c < 1024) {
                int r = c >> 3, q = c & 7;
                unsigned sa = sb + KVBASE + buf * KVBUF + r * AS + q * 16;
                CPASYNC16(sa, kk16 + (size_t)(kt * 128 + r) * DM + q * 8);
            } else {
                int c2 = c - 1024;
                int r = c2 >> 4, q = c2 & 15;
                unsigned sa = sb + KVBASE + buf * KVBUF + K_ARR + r * VS + q * 16;
                CPASYNC16(sa, vt + (size_t)r * 2048 + kt * 128 + q * 8);
            }
        }
        CPCOMMIT();
    };

    fillkv(0, 0);
    #pragma unroll 1
    for (int kt = 0; kt < nk; kt++) {
        const int buf = kt & 1;
        if (kt + 1 < nk) { fillkv(buf ^ 1, kt + 1); CPWAIT1(); }
        else             { CPWAIT0(); }
        __syncthreads();

        const unsigned Kb = sb + KVBASE + buf * KVBUF;
        const unsigned Vb = Kb + K_ARR;

        #pragma unroll
        for (int sub = 0; sub < 2; sub++) {
            float s[8][4];
            #pragma unroll
            for (int j = 0; j < 8; j++)
                #pragma unroll
                for (int e = 0; e < 4; e++) s[j][e] = 0.f;

            #pragma unroll
            for (int ks = 0; ks < 4; ks++) {
                const int kb = ks * 32;
                #pragma unroll
                for (int jj = 0; jj < 4; jj++) {
                    unsigned baddr = Kb + (sub * 64 + jj * 16 + (lane & 7)
                                     + ((lane >> 4) & 1) * 8) * AS
                                     + kb + ((lane >> 3) & 1) * 16;
                    unsigned b0, b1, b2, b3;
                    ldmx4(baddr, b0, b1, b2, b3);
                    mmafp16(s[jj * 2],     qf[ks], b0, b1);
                    mmafp16(s[jj * 2 + 1], qf[ks], b2, b3);
                }
            }

            if (kt == qt) {
                const int r0 = qt * 128 + w * 16 + (lane >> 2), r1 = r0 + 8;
                #pragma unroll
                for (int j = 0; j < 8; j++) {
                    const int cb = kt * 128 + sub * 64 + j * 8 + (lane & 3) * 2;
                    if (cb     > r0) s[j][0] = MASKV;
                    if (cb + 1 > r0) s[j][1] = MASKV;
                    if (cb     > r1) s[j][2] = MASKV;
                    if (cb + 1 > r1) s[j][3] = MASKV;
                }
            }

            unsigned ph[8][2];
            #pragma unroll
            for (int j = 0; j < 8; j++) {
                ph[j][0] = ex2h2(cvt_f16x2(s[j][0], s[j][1]));
                ph[j][1] = ex2h2(cvt_f16x2(s[j][2], s[j][3]));
            }

            #pragma unroll
            for (int kk = 0; kk < 4; kk++) {
                const int t0 = kk * 2, t1 = kk * 2 + 1;
                unsigned pA[4] = {ph[t0][0], ph[t0][1], ph[t1][0], ph[t1][1]};
                mmafp16(lacc, pA, ONESH2, ONESH2);
                #pragma unroll
                for (int jj = 0; jj < 4; jj++) {
                    unsigned baddr = Vb + (jj * 16 + (lane & 7)
                                     + ((lane >> 4) & 1) * 8) * VS
                                     + sub * 128 + kk * 32 + ((lane >> 3) & 1) * 16;
                    unsigned b0, b1, b2, b3;
                    ldmx4(baddr, b0, b1, b2, b3);
                    mmafp16(o[jj * 2],     pA, b0, b1);
                    mmafp16(o[jj * 2 + 1], pA, b2, b3);
                }
            }
        }
        __syncthreads();
    }

    const float inv0 = 1.0f / lacc[0], inv1 = 1.0f / lacc[2];
    const size_t row0 = qrow0 + w * 16 + (lane >> 2);
    #pragma unroll
    for (int j = 0; j < 8; j++) {
        const size_t col = hoff + j * 8 + (lane & 3) * 2;
        *reinterpret_cast<__half2*>(&g_z16[row0 * DM + col]) =
            __floats2half2_rn(o[j][0] * inv0, o[j][1] * inv0);
        *reinterpret_cast<__half2*>(&g_z16[(row0 + 8) * DM + col]) =
            __floats2half2_rn(o[j][2] * inv1, o[j][3] * inv1);
    }
}

// ---------------------------------------------------------------------------
extern "C" void kernel_launch(void* const* d_in, const int* in_sizes, int n_in,
                              void* d_out, int out_size)
{
    (void)in_sizes; (void)n_in; (void)out_size;
    const float* x  = (const float*)d_in[0];
    const float* WQ = (const float*)d_in[1];
    const float* bQ = (const float*)d_in[2];
    const float* WK = (const float*)d_in[3];
    const float* bK = (const float*)d_in[4];
    const float* WV = (const float*)d_in[5];
    const float* bV = (const float*)d_in[6];
    const float* WO = (const float*)d_in[7];
    const float* bO = (const float*)d_in[8];
    float* out = (float*)d_out;

    cudaFuncSetAttribute(gemm_mma, cudaFuncAttributeMaxDynamicSharedMemorySize, SMEM_G);
    cudaFuncSetAttribute(attn_mma, cudaFuncAttributeMaxDynamicSharedMemorySize, SMEM_A);

    __half *x16, *z16;
    cudaGetSymbolAddress((void**)&x16, g_x16);
    cudaGetSymbolAddress((void**)&z16, g_z16);

    prep<<<8192, 256>>>(x, WQ, WK, WV, WO);

    gemm_mma<<<dim3(8, 64, 3), 256, SMEM_G>>>(x16, bQ, bK, bV, nullptr, 0);

    attn_mma<<<dim3(16, 64), 256, SMEM_A>>>();

    gemm_mma<<<dim3(8, 64, 1), 256, SMEM_G>>>(z16, bO, bO, bO, out, 1);
}

// round 17
// speedup vs baseline: 1.1251x; 1.0083x over previous
#include <cuda_runtime.h>
#include <cuda_bf16.h>
#include <cuda_fp16.h>

// ---------------------------------------------------------------------------
// Attention_9947144257674 — round 17
//   - attention: 3-deep KV cp.async ring (Q staged in ring slot 2 during
//     prologue; 105KB smem, still 2 CTAs/SM) -> 2 tiles always in flight
//   - QKV gemm: z-slice fastest block index -> A-tile triple co-scheduled
//     (L2 reuse). Numerics identical (rel_err 5.3231e-4).
// ---------------------------------------------------------------------------

#define BSROWS 8192
#define DM     1024

__device__ __half g_x16 [(size_t)BSROWS * DM];
__device__ __half g_wt16[(size_t)4 * DM * DM];   // [slice][c][e]
__device__ __half g_q16 [(size_t)BSROWS * DM];   // prescaled Q
__device__ __half g_k16 [(size_t)BSROWS * DM];
__device__ __half g_vt16[(size_t)64 * 64 * 2048];// V^T [b*16+h][d][s]
__device__ __half g_z16 [(size_t)BSROWS * DM];

// ---------------------------------------------------------------------------
__device__ __forceinline__ unsigned smem_u32(const void* p) {
    unsigned a;
    asm("{ .reg .u64 t; cvta.to.shared.u64 t, %1; cvt.u32.u64 %0, t; }"
        : "=r"(a) : "l"(p));
    return a;
}

__device__ __forceinline__ void ldmx4(unsigned addr, unsigned& r0, unsigned& r1,
                                      unsigned& r2, unsigned& r3) {
    asm volatile("ldmatrix.sync.aligned.m8n8.x4.shared.b16 {%0,%1,%2,%3}, [%4];"
                 : "=r"(r0), "=r"(r1), "=r"(r2), "=r"(r3) : "r"(addr));
}

__device__ __forceinline__ void mmafp16(float* c, const unsigned* a,
                                        unsigned b0, unsigned b1) {
    asm volatile(
        "mma.sync.aligned.m16n8k16.row.col.f32.f16.f16.f32 "
        "{%0,%1,%2,%3}, {%4,%5,%6,%7}, {%8,%9}, {%0,%1,%2,%3};"
        : "+f"(c[0]), "+f"(c[1]), "+f"(c[2]), "+f"(c[3])
        : "r"(a[0]), "r"(a[1]), "r"(a[2]), "r"(a[3]), "r"(b0), "r"(b1));
}

#define CPASYNC16(sa, g) \
    asm volatile("cp.async.cg.shared.global [%0], [%1], 16;" :: "r"(sa), "l"(g) : "memory")
#define CPCOMMIT() asm volatile("cp.async.commit_group;" ::: "memory")
#define CPWAIT0()  asm volatile("cp.async.wait_group 0;" ::: "memory")
#define CPWAIT1()  asm volatile("cp.async.wait_group 1;" ::: "memory")

__device__ __forceinline__ unsigned cvt_f16x2(float lo, float hi) {
    unsigned r;
    asm("cvt.rn.f16x2.f32 %0, %1, %2;" : "=r"(r) : "f"(hi), "f"(lo));
    return r;
}
__device__ __forceinline__ unsigned ex2h2(unsigned x) {
    unsigned y;
    asm("ex2.approx.f16x2 %0, %1;" : "=r"(y) : "r"(x));
    return y;
}
#define ONESH2 0x3C003C00u

// ---------------------------------------------------------------------------
// fused prep (round-16)
// ---------------------------------------------------------------------------
__global__ __launch_bounds__(256) void prep(const float* __restrict__ x,
                                            const float* __restrict__ WQ,
                                            const float* __restrict__ WK,
                                            const float* __restrict__ WV,
                                            const float* __restrict__ WO) {
    const int bid = blockIdx.x;
    if (bid >= 4096) {
        size_t i = ((size_t)(bid - 4096) * 256 + threadIdx.x) * 8;
        float4 v0 = *reinterpret_cast<const float4*>(x + i);
        float4 v1 = *reinterpret_cast<const float4*>(x + i + 4);
        uint2 o0, o1;
        o0.x = cvt_f16x2(v0.x, v0.y); o0.y = cvt_f16x2(v0.z, v0.w);
        o1.x = cvt_f16x2(v1.x, v1.y); o1.y = cvt_f16x2(v1.z, v1.w);
        *reinterpret_cast<uint2*>(g_x16 + i)     = o0;
        *reinterpret_cast<uint2*>(g_x16 + i + 4) = o1;
        return;
    }
    const int m  = bid >> 10;
    const int c0 = ((bid >> 5) & 31) * 32;
    const int e0 = (bid & 31) * 32;
    const float* W = (m == 0) ? WQ : (m == 1) ? WK : (m == 2) ? WV : WO;
    __half* D = g_wt16 + (size_t)m * DM * DM;

    __shared__ float t[32][33];
    const int tx = threadIdx.x & 31, ty = threadIdx.x >> 5;

    #pragma unroll
    for (int j = 0; j < 4; j++) {
        int c = c0 + tx, e = e0 + ty + j * 8;
        size_t src = (m < 3)
            ? ((size_t)(c >> 6) * 65536 + (size_t)e * 64 + (c & 63))
            : ((size_t)e * 1024 + c);
        t[tx][ty + j * 8] = W[src];
    }
    __syncthreads();
    #pragma unroll
    for (int j = 0; j < 4; j++) {
        int e = e0 + tx, c = c0 + ty + j * 8;
        D[(size_t)c * 1024 + e] = __float2half_rn(t[ty + j * 8][tx]);
    }
}

// ---------------------------------------------------------------------------
// mma GEMM (round-14 core). QKV: grid (24, 64), z = blockIdx.x % 3 so the
// three slices of one (bm,bn) are co-scheduled (A-tile L2 reuse).
// ---------------------------------------------------------------------------
#define GS       144
#define GARR     18432
#define GBUF     36864
#define SMEM_G   110592
#define TSTRIDE  136

__global__ __launch_bounds__(256, 2) void gemm_mma(
    const __half* __restrict__ A16,
    const float* __restrict__ bQ, const float* __restrict__ bK,
    const float* __restrict__ bV, float* __restrict__ out_f32, int o_mode)
{
    extern __shared__ __align__(128) char sm[];
    const int tid  = threadIdx.x;
    const int lane = tid & 31, w = tid >> 5;
    const int wm = w >> 1, wn = w & 1;
    const int z  = o_mode ? 0 : ((int)blockIdx.x % 3);
    const int bn = (o_mode ? (int)blockIdx.x : (int)blockIdx.x / 3) * 128;
    const int bm = blockIdx.y * 128;

    const int slice = o_mode ? 3 : z;
    const __half* Bw = g_wt16 + (size_t)slice * DM * DM + (size_t)bn * DM;
    const __half* Aa = A16 + (size_t)bm * DM;
    const float* bias = o_mode ? bQ : (z == 0 ? bQ : (z == 1 ? bK : bV));
    const float oscale = (!o_mode && z == 0) ? (0.125f * 1.4426950408889634f) : 1.0f;

    const unsigned sbase = smem_u32(sm);

    float acc[2][8][4];
    #pragma unroll
    for (int i = 0; i < 2; i++)
        #pragma unroll
        for (int j = 0; j < 8; j++)
            #pragma unroll
            for (int e = 0; e < 4; e++) acc[i][j][e] = 0.f;

    const __half* srcs[2] = {Aa, Bw};

    auto fill = [&](int buf, int k0) {
        #pragma unroll
        for (int i = 0; i < 8; i++) {
            int c = tid + i * 256;
            int a = c >> 10;
            int row = (c >> 3) & 127, q = c & 7;
            unsigned sa = sbase + buf * GBUF + a * GARR + row * GS + q * 16;
            CPASYNC16(sa, srcs[a] + (size_t)row * DM + k0 + q * 8);
        }
        CPCOMMIT();
    };

    fill(0, 0);
    fill(1, 64);
    int buf = 0;
    #pragma unroll 1
    for (int ci = 0; ci < 16; ci++) {
        CPWAIT1();
        __syncthreads();

        const unsigned Ab = sbase + buf * GBUF;
        const unsigned Bb = Ab + GARR;
        #pragma unroll
        for (int ks = 0; ks < 4; ks++) {
            const int kb = ks * 32;
            unsigned ah[2][4];
            #pragma unroll
            for (int i = 0; i < 2; i++) {
                unsigned aaddr = Ab + (wm * 32 + i * 16 + (lane & 15)) * GS + kb
                                 + ((lane >> 4) & 1) * 16;
                ldmx4(aaddr, ah[i][0], ah[i][1], ah[i][2], ah[i][3]);
            }
            #pragma unroll
            for (int jj = 0; jj < 4; jj++) {
                unsigned baddr = Bb + (wn * 64 + jj * 16 + (lane & 7)
                                 + ((lane >> 4) & 1) * 8) * GS + kb
                                 + ((lane >> 3) & 1) * 16;
                unsigned b0, b1, b2, b3;
                ldmx4(baddr, b0, b1, b2, b3);
                #pragma unroll
                for (int i = 0; i < 2; i++) {
                    mmafp16(acc[i][jj * 2],     ah[i], b0, b1);
                    mmafp16(acc[i][jj * 2 + 1], ah[i], b2, b3);
                }
            }
        }

        if (ci + 2 < 16) fill((buf + 2) % 3, (ci + 2) * 64);
        buf = (buf + 1) % 3;
    }
    CPWAIT0();
    __syncthreads();

    const bool vmode = (!o_mode && z == 2);
    __half* stg = reinterpret_cast<__half*>(sm);

    #pragma unroll
    for (int i = 0; i < 2; i++) {
        const int rl = wm * 32 + i * 16 + (lane >> 2);
        const int row = bm + rl;
        #pragma unroll
        for (int j = 0; j < 8; j++) {
            const int cl = wn * 64 + j * 8 + (lane & 3) * 2;
            const int col = bn + cl;
            float v0 = (acc[i][j][0] + bias[col])     * oscale;
            float v1 = (acc[i][j][1] + bias[col + 1]) * oscale;
            float v2 = (acc[i][j][2] + bias[col])     * oscale;
            float v3 = (acc[i][j][3] + bias[col + 1]) * oscale;
            if (o_mode) {
                float2 a = {v0, v1}, b2 = {v2, v3};
                *reinterpret_cast<float2*>(&out_f32[(size_t)row * DM + col]) = a;
                *reinterpret_cast<float2*>(&out_f32[(size_t)(row + 8) * DM + col]) = b2;
            } else if (vmode) {
                stg[cl * TSTRIDE + rl]           = __float2half_rn(v0);
                stg[(cl + 1) * TSTRIDE + rl]     = __float2half_rn(v1);
                stg[cl * TSTRIDE + rl + 8]       = __float2half_rn(v2);
                stg[(cl + 1) * TSTRIDE + rl + 8] = __float2half_rn(v3);
            } else {
                __half* dst = (z == 0) ? g_q16 : g_k16;
                *reinterpret_cast<__half2*>(&dst[(size_t)row * DM + col]) =
                    __floats2half2_rn(v0, v1);
                *reinterpret_cast<__half2*>(&dst[(size_t)(row + 8) * DM + col]) =
                    __floats2half2_rn(v2, v3);
            }
        }
    }

    if (vmode) {
        __syncthreads();
        const int bb = bm >> 11;
        const int c  = tid >> 1, hf = tid & 1;
        const int gcol = bn + c;
        const int hh = gcol >> 6, d = gcol & 63;
        const __half* srcr = stg + c * TSTRIDE + hf * 64;
        __half* dstr = g_vt16 + ((size_t)(bb * 16 + hh) * 64 + d) * 2048
                       + (bm & 2047) + hf * 64;
        #pragma unroll
        for (int u = 0; u < 8; u++)
            *reinterpret_cast<uint4*>(dstr + u * 8) =
                *reinterpret_cast<const uint4*>(srcr + u * 8);
    }
}

// ---------------------------------------------------------------------------
// flash attention: BQ=128, 8 warps x 16 q-rows, 128-key tiles (two 64-key
// sub-passes), 3-deep KV cp.async ring. Q staged in ring slot 2 at prologue.
// smem: 3 x (K 128x144 + V^T 64x272) = 107520
// ---------------------------------------------------------------------------
#define AS      144
#define VS      272
#define K_ARR   18432
#define V_ARR   17408
#define KVBUF   (K_ARR + V_ARR)  // 35840
#define SMEM_A  107520
#define MASKV   (-60000.0f)

__global__ __launch_bounds__(256, 2) void attn_mma()
{
    extern __shared__ __align__(128) char sm[];
    const int tid = threadIdx.x, lane = tid & 31, w = tid >> 5;
    const int qt = (int)gridDim.x - 1 - (int)blockIdx.x;
    const int bh = blockIdx.y;
    const int b = bh >> 4, h = bh & 15;

    const unsigned sb = smem_u32(sm);
    const size_t qrow0 = (size_t)b * 2048 + (size_t)qt * 128;
    const size_t hoff  = (size_t)h * 64;

    // ---- Q staged in ring slot 2 (refilled only from kt=2 onward) ----
    const unsigned Qb = sb + 2 * KVBUF;
    {
        const __half* q16 = g_q16 + qrow0 * DM + hoff;
        #pragma unroll
        for (int i = 0; i < 4; i++) {
            int c = tid + i * 256;
            int r = c >> 3, q = c & 7;
            unsigned sa = Qb + r * AS + q * 16;
            CPASYNC16(sa, q16 + (size_t)r * DM + q * 8);
        }
        CPCOMMIT(); CPWAIT0();
        __syncthreads();
    }
    unsigned qf[4][4];
    #pragma unroll
    for (int ks = 0; ks < 4; ks++) {
        unsigned aaddr = Qb + (w * 16 + (lane & 15)) * AS + ks * 32
                         + ((lane >> 4) & 1) * 16;
        ldmx4(aaddr, qf[ks][0], qf[ks][1], qf[ks][2], qf[ks][3]);
    }

    float o[8][4];
    #pragma unroll
    for (int j = 0; j < 8; j++)
        #pragma unroll
        for (int e = 0; e < 4; e++) o[j][e] = 0.f;
    float lacc[4] = {0.f, 0.f, 0.f, 0.f};

    const __half* kk16 = g_k16 + (size_t)b * 2048 * DM + hoff;
    const __half* vt   = g_vt16 + (size_t)bh * 64 * 2048;

    const int nk = qt + 1;

    auto fillkv = [&](int buf, int kt) {
        #pragma unroll
        for (int i = 0; i < 8; i++) {
            int c = tid + i * 256;
            if (c < 1024) {
                int r = c >> 3, q = c & 7;
                unsigned sa = sb + buf * KVBUF + r * AS + q * 16;
                CPASYNC16(sa, kk16 + (size_t)(kt * 128 + r) * DM + q * 8);
            } else {
                int c2 = c - 1024;
                int r = c2 >> 4, q = c2 & 15;
                unsigned sa = sb + buf * KVBUF + K_ARR + r * VS + q * 16;
                CPASYNC16(sa, vt + (size_t)r * 2048 + kt * 128 + q * 8);
            }
        }
        CPCOMMIT();
    };

    fillkv(0, 0);
    if (nk > 1) fillkv(1, 1);
    int buf = 0;
    #pragma unroll 1
    for (int kt = 0; kt < nk; kt++) {
        if (kt + 1 < nk) { CPWAIT1(); }
        else             { CPWAIT0(); }
        __syncthreads();   // also guards slot (buf+2)%3 refill below

        const unsigned Kb = sb + buf * KVBUF;
        const unsigned Vb = Kb + K_ARR;

        #pragma unroll
        for (int sub = 0; sub < 2; sub++) {
            float s[8][4];
            #pragma unroll
            for (int j = 0; j < 8; j++)
                #pragma unroll
                for (int e = 0; e < 4; e++) s[j][e] = 0.f;

            #pragma unroll
            for (int ks = 0; ks < 4; ks++) {
                const int kb = ks * 32;
                #pragma unroll
                for (int jj = 0; jj < 4; jj++) {
                    unsigned baddr = Kb + (sub * 64 + jj * 16 + (lane & 7)
                                     + ((lane >> 4) & 1) * 8) * AS
                                     + kb + ((lane >> 3) & 1) * 16;
                    unsigned b0, b1, b2, b3;
                    ldmx4(baddr, b0, b1, b2, b3);
                    mmafp16(s[jj * 2],     qf[ks], b0, b1);
                    mmafp16(s[jj * 2 + 1], qf[ks], b2, b3);
                }
            }

            if (kt == qt) {
                const int r0 = qt * 128 + w * 16 + (lane >> 2), r1 = r0 + 8;
                #pragma unroll
                for (int j = 0; j < 8; j++) {
                    const int cb = kt * 128 + sub * 64 + j * 8 + (lane & 3) * 2;
                    if (cb     > r0) s[j][0] = MASKV;
                    if (cb + 1 > r0) s[j][1] = MASKV;
                    if (cb     > r1) s[j][2] = MASKV;
                    if (cb + 1 > r1) s[j][3] = MASKV;
                }
            }

            unsigned ph[8][2];
            #pragma unroll
            for (int j = 0; j < 8; j++) {
                ph[j][0] = ex2h2(cvt_f16x2(s[j][0], s[j][1]));
                ph[j][1] = ex2h2(cvt_f16x2(s[j][2], s[j][3]));
            }

            #pragma unroll
            for (int kk = 0; kk < 4; kk++) {
                const int t0 = kk * 2, t1 = kk * 2 + 1;
                unsigned pA[4] = {ph[t0][0], ph[t0][1], ph[t1][0], ph[t1][1]};
                mmafp16(lacc, pA, ONESH2, ONESH2);
                #pragma unroll
                for (int jj = 0; jj < 4; jj++) {
                    unsigned baddr = Vb + (jj * 16 + (lane & 7)
                                     + ((lane >> 4) & 1) * 8) * VS
                                     + sub * 128 + kk * 32 + ((lane >> 3) & 1) * 16;
                    unsigned b0, b1, b2, b3;
                    ldmx4(baddr, b0, b1, b2, b3);
                    mmafp16(o[jj * 2],     pA, b0, b1);
                    mmafp16(o[jj * 2 + 1], pA, b2, b3);
                }
            }
        }

        if (kt + 2 < nk) fillkv((buf + 2) % 3, kt + 2);
        buf = (buf + 1) % 3;
    }

    const float inv0 = 1.0f / lacc[0], inv1 = 1.0f / lacc[2];
    const size_t row0 = qrow0 + w * 16 + (lane >> 2);
    #pragma unroll
    for (int j = 0; j < 8; j++) {
        const size_t col = hoff + j * 8 + (lane & 3) * 2;
        *reinterpret_cast<__half2*>(&g_z16[row0 * DM + col]) =
            __floats2half2_rn(o[j][0] * inv0, o[j][1] * inv0);
        *reinterpret_cast<__half2*>(&g_z16[(row0 + 8) * DM + col]) =
            __floats2half2_rn(o[j][2] * inv1, o[j][3] * inv1);
    }
}

// ---------------------------------------------------------------------------
extern "C" void kernel_launch(void* const* d_in, const int* in_sizes, int n_in,
                              void* d_out, int out_size)
{
    (void)in_sizes; (void)n_in; (void)out_size;
    const float* x  = (const float*)d_in[0];
    const float* WQ = (const float*)d_in[1];
    const float* bQ = (const float*)d_in[2];
    const float* WK = (const float*)d_in[3];
    const float* bK = (const float*)d_in[4];
    const float* WV = (const float*)d_in[5];
    const float* bV = (const float*)d_in[6];
    const float* WO = (const float*)d_in[7];
    const float* bO = (const float*)d_in[8];
    float* out = (float*)d_out;

    cudaFuncSetAttribute(gemm_mma, cudaFuncAttributeMaxDynamicSharedMemorySize, SMEM_G);
    cudaFuncSetAttribute(attn_mma, cudaFuncAttributeMaxDynamicSharedMemorySize, SMEM_A);

    __half *x16, *z16;
    cudaGetSymbolAddress((void**)&x16, g_x16);
    cudaGetSymbolAddress((void**)&z16, g_z16);

    prep<<<8192, 256>>>(x, WQ, WK, WV, WO);

    // QKV: z fastest-varying -> A-tile triple co-scheduled
    gemm_mma<<<dim3(24, 64, 1), 256, SMEM_G>>>(x16, bQ, bK, bV, nullptr, 0);

    attn_mma<<<dim3(16, 64), 256, SMEM_A>>>();

    gemm_mma<<<dim3(8, 64, 1), 256, SMEM_G>>>(z16, bO, bO, bO, out, 1);
}